// round 16
// baseline (speedup 1.0000x reference)
#include <cuda_runtime.h>
#include <cstdint>

#define NBS 100000
#define NGS 20000
#define EL  1000000
#define EX  200000
#define CAP 64

#define TM 128
#define BUSB ((NBS + TM - 1) / TM)   // 782
#define GENB ((NGS + TM - 1) / TM)   // 157

// ---------------- scratch (static device globals; no allocation) ----------------
// Ping-pong feature buffers: layer 1 writes g_hb/g_hg, layer 2 reads them and
// writes g_hb2/g_hg2 (inline gather reads neighbors across the whole graph, so
// a layer must never write the buffer it reads).
__device__ float g_hb[NBS * 64];
__device__ float g_hg[NGS * 64];
__device__ float g_hb2[NBS * 64];
__device__ float g_hg2[NGS * 64];
__device__ int   g_cntL[NBS], g_cntG[NBS], g_cntB[NGS];
__device__ int   g_csrL[(size_t)NBS * CAP];
__device__ int   g_csrG[(size_t)NBS * CAP];
__device__ int   g_csrB[(size_t)NGS * CAP];
__device__ float g_pool[128];

// ---------------- f32x2 helpers ----------------
__device__ __forceinline__ unsigned long long packf2(float v) {
    unsigned long long r;
    asm("mov.b64 %0, {%1, %1};" : "=l"(r) : "f"(v));
    return r;
}
__device__ __forceinline__ unsigned long long packf2b(float a, float b) {
    unsigned long long r;
    asm("mov.b64 %0, {%1, %2};" : "=l"(r) : "f"(a), "f"(b));
    return r;
}
__device__ __forceinline__ void fma2(unsigned long long& acc,
                                     unsigned long long a, unsigned long long b) {
    asm("fma.rn.f32x2 %0, %1, %2, %0;" : "+l"(acc) : "l"(a), "l"(b));
}
__device__ __forceinline__ void unpackf2(unsigned long long v, float& a, float& b) {
    asm("mov.b64 {%0, %1}, %2;" : "=f"(a), "=f"(b) : "l"(v));
}

// ---------------- CSR build (cnt arrays zero at module load and re-zeroed by
// k_pool_all each call -> graph replays stay correct) ----------------
__global__ void k_fill_line(const int* __restrict__ ls, const int* __restrict__ ldst)
{
    int i = blockIdx.x * blockDim.x + threadIdx.x;
    if (i < EL) {
        int d = __ldg(&ldst[i]);
        int pos = atomicAdd(&g_cntL[d], 1);
        if (pos < CAP) g_csrL[(size_t)d * CAP + pos] = __ldg(&ls[i]);
    }
}
__global__ void k_fill_x(const int* __restrict__ gs, const int* __restrict__ gd,
                         const int* __restrict__ bs, const int* __restrict__ bd)
{
    int i = blockIdx.x * blockDim.x + threadIdx.x;
    if (i < EX) {
        int d = __ldg(&gd[i]);
        int pos = atomicAdd(&g_cntG[d], 1);
        if (pos < CAP) g_csrG[(size_t)d * CAP + pos] = __ldg(&gs[i]);
        int d2 = __ldg(&bd[i]);
        int pos2 = atomicAdd(&g_cntB[d2], 1);
        if (pos2 < CAP) g_csrB[(size_t)d2 * CAP + pos2] = __ldg(&bs[i]);
    }
}

// ---------------- fused update with INLINE gather (bus + gen) ----------------
// bus: new_hb = relu(hb@Wsb + mean_line(hb)@Wl + mean_g2b(hg)@Wg2b + bsb), K=192
// gen: new_hg = relu(hg@Wsg + mean_b2g(hb)@Wb2g + bsg),                   K=128
// The mean-aggregation segments are gathered INLINE in the prefetch slot
// (CSR bucket loop), overlapped with the 16-k FFMA2 compute window.
// hbin/hgin: layer inputs; outb/outg: layer outputs (never aliased with inputs).
__global__ void __launch_bounds__(256, 3) k_fused(
    const float* hbin, const float* hgin,
    float* outb, float* outg,
    const float* __restrict__ Wsb, const float* __restrict__ Wl,
    const float* __restrict__ Wg2b, const float* __restrict__ bsb,
    const float* __restrict__ Wsg, const float* __restrict__ Wb2g,
    const float* __restrict__ bsg)
{
    extern __shared__ float sm[];
    float* sW = sm;                 // [<=192*64]
    float* sB = sm + 12288;         // [64]
    float* sX = sm + 12288 + 64;    // [2][16][132]

    int t = threadIdx.x;
    bool bus = blockIdx.x < BUSB;

    if (bus) {
        for (int idx = t; idx < 4096; idx += 256) {
            sW[idx]        = Wsb[idx];
            sW[4096 + idx] = Wl[idx];
            sW[8192 + idx] = Wg2b[idx];
        }
        if (t < 64) sB[t] = bsb[t];
    } else {
        for (int idx = t; idx < 4096; idx += 256) {
            sW[idx]        = Wsg[idx];
            sW[4096 + idx] = Wb2g[idx];
        }
        if (t < 64) sB[t] = bsg[t];
    }

    int tile = bus ? blockIdx.x : blockIdx.x - BUSB;
    int n    = bus ? NBS : NGS;
    int row0 = tile * TM;
    const float* hbp = hbin;
    const float* hgp = hgin;
    const float* hsrc = bus ? hbp : hgp;
    int nkc = bus ? 12 : 8;      // chunks of 16 k

    // staging ids: thread stages rows (r_a, r_b) for float4 slot kq
    int r_a = t >> 2;            // 0..63
    int r_b = r_a + 64;          // 64..127
    int kq  = t & 3;
    int grA = min(row0 + r_a, n - 1);
    int grB = min(row0 + r_b, n - 1);

    // compute ids: thread owns rows [tr*8, tr*8+8), cols [tc*4, tc*4+4)
    int tc = t & 15;
    int tr = t >> 4;

    __syncthreads();   // sW/sB visible

    unsigned long long bias0 = packf2b(sB[tc * 4],     sB[tc * 4 + 1]);
    unsigned long long bias1 = packf2b(sB[tc * 4 + 2], sB[tc * 4 + 3]);
    unsigned long long acc[16];
#pragma unroll
    for (int r = 0; r < 8; r++) { acc[2 * r] = bias0; acc[2 * r + 1] = bias1; }

    // prefetch chunk 0 (always segment 0 = self features)
    float4 va = *(const float4*)(hsrc + (size_t)grA * 64 + kq * 4);
    float4 vb = *(const float4*)(hsrc + (size_t)grB * 64 + kq * 4);

    for (int kc = 0; kc < nkc; kc++) {
        float* xb = sX + (kc & 1) * 2112;
        xb[(kq * 4 + 0) * 132 + r_a] = va.x;
        xb[(kq * 4 + 1) * 132 + r_a] = va.y;
        xb[(kq * 4 + 2) * 132 + r_a] = va.z;
        xb[(kq * 4 + 3) * 132 + r_a] = va.w;
        xb[(kq * 4 + 0) * 132 + r_b] = vb.x;
        xb[(kq * 4 + 1) * 132 + r_b] = vb.y;
        xb[(kq * 4 + 2) * 132 + r_b] = vb.z;
        xb[(kq * 4 + 3) * 132 + r_b] = vb.w;
        __syncthreads();

        int kc1 = kc + 1;
        if (kc1 < nkc) {   // prefetch next chunk (overlaps with compute below)
            int seg = kc1 >> 2;          // 0: self, 1: agg1, 2: aggG (bus only)
            int kk  = (kc1 & 3) * 16 + kq * 4;
            if (seg == 0) {
                va = *(const float4*)(hsrc + (size_t)grA * 64 + kk);
                vb = *(const float4*)(hsrc + (size_t)grB * 64 + kk);
            } else {
                // inline CSR gather: mean over src rows of this edge type
                const float* srcf;
                const int* cnt;
                const int* csr;
                if (!bus)          { srcf = hbp; cnt = g_cntB; csr = g_csrB; }
                else if (seg == 1) { srcf = hbp; cnt = g_cntL; csr = g_csrL; }
                else               { srcf = hgp; cnt = g_cntG; csr = g_csrG; }
                int dA = min(__ldg(&cnt[grA]), CAP);
                int dB = min(__ldg(&cnt[grB]), CAP);
                const int* bA = csr + (size_t)grA * CAP;
                const int* bB = csr + (size_t)grB * CAP;
                float4 a = make_float4(0.f, 0.f, 0.f, 0.f);
                float4 b = make_float4(0.f, 0.f, 0.f, 0.f);
                int dm = max(dA, dB);
#pragma unroll 2
                for (int e = 0; e < dm; e++) {
                    if (e < dA) {
                        int s = __ldg(&bA[e]);
                        float4 v = *(const float4*)(srcf + (size_t)s * 64 + kk);
                        a.x += v.x; a.y += v.y; a.z += v.z; a.w += v.w;
                    }
                    if (e < dB) {
                        int s = __ldg(&bB[e]);
                        float4 v = *(const float4*)(srcf + (size_t)s * 64 + kk);
                        b.x += v.x; b.y += v.y; b.z += v.z; b.w += v.w;
                    }
                }
                float iA = 1.f / (float)max(dA, 1);
                float iB = 1.f / (float)max(dB, 1);
                va.x = a.x * iA; va.y = a.y * iA; va.z = a.z * iA; va.w = a.w * iA;
                vb.x = b.x * iB; vb.y = b.y * iB; vb.z = b.z * iB; vb.w = b.w * iB;
            }
        }

        const float* wk = sW + kc * 1024 + tc * 4;   // 16 k-rows of 64 cols
        const float* xk = xb + tr * 8;
#pragma unroll
        for (int k = 0; k < 16; k++) {
            float4 w  = *(const float4*)(wk + k * 64);
            float4 x0 = *(const float4*)(xk + k * 132);
            float4 x1 = *(const float4*)(xk + k * 132 + 4);
            unsigned long long w01 = packf2b(w.x, w.y);
            unsigned long long w23 = packf2b(w.z, w.w);
            unsigned long long xx;
            xx = packf2(x0.x); fma2(acc[0],  xx, w01); fma2(acc[1],  xx, w23);
            xx = packf2(x0.y); fma2(acc[2],  xx, w01); fma2(acc[3],  xx, w23);
            xx = packf2(x0.z); fma2(acc[4],  xx, w01); fma2(acc[5],  xx, w23);
            xx = packf2(x0.w); fma2(acc[6],  xx, w01); fma2(acc[7],  xx, w23);
            xx = packf2(x1.x); fma2(acc[8],  xx, w01); fma2(acc[9],  xx, w23);
            xx = packf2(x1.y); fma2(acc[10], xx, w01); fma2(acc[11], xx, w23);
            xx = packf2(x1.z); fma2(acc[12], xx, w01); fma2(acc[13], xx, w23);
            xx = packf2(x1.w); fma2(acc[14], xx, w01); fma2(acc[15], xx, w23);
        }
        // single sync per iter is safe: next iter's STS targets the other buffer
    }

    // epilogue: relu + store 8x4 tile (to the ping-pong OUTPUT buffer)
    float* outp = bus ? outb : outg;
#pragma unroll
    for (int r = 0; r < 8; r++) {
        int rr = row0 + tr * 8 + r;
        if (rr < n) {
            float4 o;
            unpackf2(acc[2 * r],     o.x, o.y);
            unpackf2(acc[2 * r + 1], o.z, o.w);
            o.x = fmaxf(o.x, 0.f); o.y = fmaxf(o.y, 0.f);
            o.z = fmaxf(o.z, 0.f); o.w = fmaxf(o.w, 0.f);
            *(float4*)(outp + (size_t)rr * 64 + tc * 4) = o;
        }
    }
}

// ---------------- sum pooling (bus + gen; reads layer-2 buffers) + cnt re-zero ----
__global__ void k_pool_all() {
    // re-zero CSR counters (consumed this call; next call/replay needs zeros)
    for (int i = blockIdx.x * 256 + threadIdx.x; i < NBS; i += 300 * 256) {
        g_cntL[i] = 0; g_cntG[i] = 0;
        if (i < NGS) g_cntB[i] = 0;
    }

    bool bus = blockIdx.x < 240;
    const float* h = bus ? g_hb2 : g_hg2;
    int n = bus ? NBS : NGS;
    int obase = bus ? 0 : 64;
    int bid = bus ? blockIdx.x : blockIdx.x - 240;
    int nb  = bus ? 240 : 60;

    int col = threadIdx.x & 63, grp = threadIdx.x >> 6;
    float s = 0.f;
    for (int r = bid * 4 + grp; r < n; r += nb * 4)
        s += h[(size_t)r * 64 + col];
    __shared__ float sh[256];
    sh[threadIdx.x] = s;
    __syncthreads();
    if (grp == 0)
        atomicAdd(&g_pool[obase + col],
                  sh[col] + sh[col + 64] + sh[col + 128] + sh[col + 192]);
}

// ---------------- MLP head (also re-zeroes g_pool for next call) ----------------
__global__ void k_head(const float* __restrict__ W_h, const float* __restrict__ b_h,
                       const float* __restrict__ W_o, const float* __restrict__ b_o,
                       float* __restrict__ out)
{
    __shared__ float sg[128], st[64];
    int t = threadIdx.x;   // 128 threads
    sg[t] = g_pool[t];
    __syncthreads();
    g_pool[t] = 0.f;       // consumed; restore zero-invariant for replay
    if (t < 64) {
        float a = b_h[t];
#pragma unroll
        for (int i = 0; i < 128; i++) a += sg[i] * W_h[i * 64 + t];
        st[t] = fmaxf(a, 0.f);
    }
    __syncthreads();
    if (t < 16) {
        float o = b_o[t];
#pragma unroll
        for (int j = 0; j < 64; j++) o += st[j] * W_o[j * 16 + t];
        out[t] = o;
    }
}

// ---------------- launch ----------------
extern "C" void kernel_launch(void* const* d_in, const int* in_sizes, int n_in,
                              void* d_out, int out_size)
{
    const float* x_bus   = (const float*)d_in[0];
    const float* x_gen   = (const float*)d_in[1];
    const int* line_src  = (const int*)d_in[2];
    const int* line_dst  = (const int*)d_in[3];
    const int* g2b_src   = (const int*)d_in[4];
    const int* g2b_dst   = (const int*)d_in[5];
    const int* b2g_src   = (const int*)d_in[6];
    const int* b2g_dst   = (const int*)d_in[7];
    const float* Wsb[2]  = { (const float*)d_in[8],  (const float*)d_in[15] };
    const float* Wsg[2]  = { (const float*)d_in[9],  (const float*)d_in[16] };
    const float* Wl[2]   = { (const float*)d_in[10], (const float*)d_in[17] };
    const float* Wg2b[2] = { (const float*)d_in[11], (const float*)d_in[18] };
    const float* Wb2g[2] = { (const float*)d_in[12], (const float*)d_in[19] };
    const float* bsb[2]  = { (const float*)d_in[13], (const float*)d_in[20] };
    const float* bsg[2]  = { (const float*)d_in[14], (const float*)d_in[21] };
    const float* W_h = (const float*)d_in[22];
    const float* b_h = (const float*)d_in[23];
    const float* W_o = (const float*)d_in[24];
    const float* b_o = (const float*)d_in[25];

    // device-symbol addresses for the ping-pong buffers
    float *hb1, *hg1, *hb2, *hg2;
    cudaGetSymbolAddress((void**)&hb1, g_hb);
    cudaGetSymbolAddress((void**)&hg1, g_hg);
    cudaGetSymbolAddress((void**)&hb2, g_hb2);
    cudaGetSymbolAddress((void**)&hg2, g_hg2);

    const int SMEM_FUSED = (12288 + 64 + 2 * 16 * 132) * 4;   // 66304 B
    cudaFuncSetAttribute(k_fused, cudaFuncAttributeMaxDynamicSharedMemorySize,
                         SMEM_FUSED);

    // launch order chosen so launch #4 (= the ncu capture slot) is the
    // layer-2 k_fused (inline-gather version)
    k_fill_line<<<(EL + 255) / 256, 256>>>(line_src, line_dst);           // 1
    k_fill_x<<<(EX + 255) / 256, 256>>>(g2b_src, g2b_dst,                 // 2
                                        b2g_src, b2g_dst);
    k_fused<<<BUSB + GENB, 256, SMEM_FUSED>>>(x_bus, x_gen, hb1, hg1,     // 3
                                  Wsb[0], Wl[0], Wg2b[0], bsb[0],
                                  Wsg[0], Wb2g[0], bsg[0]);
    k_fused<<<BUSB + GENB, 256, SMEM_FUSED>>>(hb1, hg1, hb2, hg2,         // 4 (ncu)
                                  Wsb[1], Wl[1], Wg2b[1], bsb[1],
                                  Wsg[1], Wb2g[1], bsg[1]);
    k_pool_all<<<300, 256>>>();                                           // 5
    k_head<<<1, 128>>>(W_h, b_h, W_o, b_o, (float*)d_out);                // 6
}

// round 17
// speedup vs baseline: 1.4425x; 1.4425x over previous
#include <cuda_runtime.h>
#include <cstdint>

#define NBS 100000
#define NGS 20000
#define EL  1000000
#define EX  200000
#define CAP 64

#define TM 128
#define BUSB ((NBS + TM - 1) / TM)   // 782
#define GENB ((NGS + TM - 1) / TM)   // 157

// ---------------- scratch (static device globals; no allocation) ----------------
__device__ float g_hb[NBS * 64];
__device__ float g_hg[NGS * 64];
__device__ float g_aggL[NBS * 64];   // mean of hb over line edges, at bus dst
__device__ float g_aggG[NBS * 64];   // mean of hg over g2b edges, at bus dst
__device__ float g_aggB[NGS * 64];   // mean of hb over b2g edges, at gen dst
__device__ int   g_cntL[NBS], g_cntG[NBS], g_cntB[NGS];
__device__ int   g_csrL[(size_t)NBS * CAP];
__device__ int   g_csrG[(size_t)NBS * CAP];
__device__ int   g_csrB[(size_t)NGS * CAP];
__device__ float g_pool[128];

// ---------------- f32x2 helpers ----------------
__device__ __forceinline__ unsigned long long packf2(float v) {
    unsigned long long r;
    asm("mov.b64 %0, {%1, %1};" : "=l"(r) : "f"(v));
    return r;
}
__device__ __forceinline__ unsigned long long packf2b(float a, float b) {
    unsigned long long r;
    asm("mov.b64 %0, {%1, %2};" : "=l"(r) : "f"(a), "f"(b));
    return r;
}
__device__ __forceinline__ void fma2(unsigned long long& acc,
                                     unsigned long long a, unsigned long long b) {
    asm("fma.rn.f32x2 %0, %1, %2, %0;" : "+l"(acc) : "l"(a), "l"(b));
}
__device__ __forceinline__ void unpackf2(unsigned long long v, float& a, float& b) {
    asm("mov.b64 {%0, %1}, %2;" : "=f"(a), "=f"(b) : "l"(v));
}

// ---------------- CSR build: count + fill padded buckets in one pass ----------------
// cnt arrays are zero at module load and re-zeroed by k_pool_all each call,
// so graph replays stay correct.
__global__ void k_fill(const int* __restrict__ ls, const int* __restrict__ ldst,
                       const int* __restrict__ gs, const int* __restrict__ gd,
                       const int* __restrict__ bs, const int* __restrict__ bd)
{
    int i = blockIdx.x * blockDim.x + threadIdx.x;
    if (i < EL) {
        int d = __ldg(&ldst[i]);
        int pos = atomicAdd(&g_cntL[d], 1);
        if (pos < CAP) g_csrL[(size_t)d * CAP + pos] = __ldg(&ls[i]);
    }
    if (i < EX) {
        int d = __ldg(&gd[i]);
        int pos = atomicAdd(&g_cntG[d], 1);
        if (pos < CAP) g_csrG[(size_t)d * CAP + pos] = __ldg(&gs[i]);
        int d2 = __ldg(&bd[i]);
        int pos2 = atomicAdd(&g_cntB[d2], 1);
        if (pos2 < CAP) g_csrB[(size_t)d2 * CAP + pos2] = __ldg(&bs[i]);
    }
}

// ---------------- pull-mode aggregation (all 3 edge types, writes MEANS) --------
// 8 threads/node (q = float4 slot; thread covers slots q and q+8).
// int4 bucket loads (4 indices / LDG.128; buckets are 256B-aligned) + 2
// independent float4 loads per edge -> ~9 loads in flight per thread.
__global__ void __launch_bounds__(256) k_gather(const float* hb, const float* hg)
{
    int tid = blockIdx.x * 256 + threadIdx.x;
    int node = tid >> 3;
    int q = tid & 7;

    const float4* hsrc;
    const int* bucket;
    float4* aggout;
    int deg;
    const float* hbp = hb ? hb : (const float*)g_hb;
    const float* hgp = hg ? hg : (const float*)g_hg;

    if (node < NBS) {
        deg = g_cntL[node];
        bucket = g_csrL + (size_t)node * CAP;
        hsrc = (const float4*)hbp;
        aggout = (float4*)g_aggL + (size_t)node * 16;
    } else if (node < 2 * NBS) {
        int m = node - NBS;
        deg = g_cntG[m];
        bucket = g_csrG + (size_t)m * CAP;
        hsrc = (const float4*)hgp;
        aggout = (float4*)g_aggG + (size_t)m * 16;
    } else if (node < 2 * NBS + NGS) {
        int m = node - 2 * NBS;
        deg = g_cntB[m];
        bucket = g_csrB + (size_t)m * CAP;
        hsrc = (const float4*)hbp;
        aggout = (float4*)g_aggB + (size_t)m * 16;
    } else return;

    if (deg > CAP) deg = CAP;
    float4 a0 = make_float4(0.f, 0.f, 0.f, 0.f);
    float4 a1 = make_float4(0.f, 0.f, 0.f, 0.f);
    for (int e0 = 0; e0 < deg; e0 += 4) {
        int4 idx = __ldg((const int4*)(bucket + e0));
        {
            const float4* r = hsrc + (size_t)idx.x * 16;
            float4 v0 = __ldg(r + q), v1 = __ldg(r + q + 8);
            a0.x += v0.x; a0.y += v0.y; a0.z += v0.z; a0.w += v0.w;
            a1.x += v1.x; a1.y += v1.y; a1.z += v1.z; a1.w += v1.w;
        }
        if (e0 + 1 < deg) {
            const float4* r = hsrc + (size_t)idx.y * 16;
            float4 v0 = __ldg(r + q), v1 = __ldg(r + q + 8);
            a0.x += v0.x; a0.y += v0.y; a0.z += v0.z; a0.w += v0.w;
            a1.x += v1.x; a1.y += v1.y; a1.z += v1.z; a1.w += v1.w;
        }
        if (e0 + 2 < deg) {
            const float4* r = hsrc + (size_t)idx.z * 16;
            float4 v0 = __ldg(r + q), v1 = __ldg(r + q + 8);
            a0.x += v0.x; a0.y += v0.y; a0.z += v0.z; a0.w += v0.w;
            a1.x += v1.x; a1.y += v1.y; a1.z += v1.z; a1.w += v1.w;
        }
        if (e0 + 3 < deg) {
            const float4* r = hsrc + (size_t)idx.w * 16;
            float4 v0 = __ldg(r + q), v1 = __ldg(r + q + 8);
            a0.x += v0.x; a0.y += v0.y; a0.z += v0.z; a0.w += v0.w;
            a1.x += v1.x; a1.y += v1.y; a1.z += v1.z; a1.w += v1.w;
        }
    }
    float inv = 1.f / (float)max(deg, 1);
    a0.x *= inv; a0.y *= inv; a0.z *= inv; a0.w *= inv;
    a1.x *= inv; a1.y *= inv; a1.z *= inv; a1.w *= inv;
    aggout[q]     = a0;
    aggout[q + 8] = a1;
}

// ---------------- register-tiled fused update (bus + gen) ----------------
// bus: new_hb = relu(hb@Wsb + mL@Wl + mG@Wg2b + bsb), K=192
// gen: new_hg = relu(hg@Wsg + mB@Wb2g + bsg),         K=128
// (agg buffers already hold MEANS from k_gather; no scaling, no zeroing.)
__global__ void __launch_bounds__(256, 3) k_fused(
    const float* hbin, const float* hgin,
    const float* __restrict__ Wsb, const float* __restrict__ Wl,
    const float* __restrict__ Wg2b, const float* __restrict__ bsb,
    const float* __restrict__ Wsg, const float* __restrict__ Wb2g,
    const float* __restrict__ bsg)
{
    extern __shared__ float sm[];
    float* sW = sm;                 // [<=192*64]
    float* sB = sm + 12288;         // [64]
    float* sX = sm + 12288 + 64;    // [2][16][132]

    int t = threadIdx.x;
    bool bus = blockIdx.x < BUSB;

    if (bus) {
        for (int idx = t; idx < 4096; idx += 256) {
            sW[idx]        = Wsb[idx];
            sW[4096 + idx] = Wl[idx];
            sW[8192 + idx] = Wg2b[idx];
        }
        if (t < 64) sB[t] = bsb[t];
    } else {
        for (int idx = t; idx < 4096; idx += 256) {
            sW[idx]        = Wsg[idx];
            sW[4096 + idx] = Wb2g[idx];
        }
        if (t < 64) sB[t] = bsg[t];
    }

    int tile = bus ? blockIdx.x : blockIdx.x - BUSB;
    int n    = bus ? NBS : NGS;
    int row0 = tile * TM;
    const float* hsrc = bus ? (hbin ? hbin : (const float*)g_hb)
                            : (hgin ? hgin : (const float*)g_hg);
    const float* agg1 = bus ? g_aggL : g_aggB;
    int nkc = bus ? 12 : 8;      // chunks of 16 k

    // staging ids: thread stages rows (r_a, r_b) for float4 slot kq
    int r_a = t >> 2;            // 0..63
    int r_b = r_a + 64;          // 64..127
    int kq  = t & 3;
    int grA = min(row0 + r_a, n - 1);
    int grB = min(row0 + r_b, n - 1);

    // compute ids: thread owns rows [tr*8, tr*8+8), cols [tc*4, tc*4+4)
    int tc = t & 15;
    int tr = t >> 4;

    __syncthreads();   // sW/sB visible

    unsigned long long bias0 = packf2b(sB[tc * 4],     sB[tc * 4 + 1]);
    unsigned long long bias1 = packf2b(sB[tc * 4 + 2], sB[tc * 4 + 3]);
    unsigned long long acc[16];
#pragma unroll
    for (int r = 0; r < 8; r++) { acc[2 * r] = bias0; acc[2 * r + 1] = bias1; }

    // prefetch chunk 0 (always segment 0 = h)
    float4 va = *(const float4*)(hsrc + (size_t)grA * 64 + kq * 4);
    float4 vb = *(const float4*)(hsrc + (size_t)grB * 64 + kq * 4);

    for (int kc = 0; kc < nkc; kc++) {
        float* xb = sX + (kc & 1) * 2112;
        xb[(kq * 4 + 0) * 132 + r_a] = va.x;
        xb[(kq * 4 + 1) * 132 + r_a] = va.y;
        xb[(kq * 4 + 2) * 132 + r_a] = va.z;
        xb[(kq * 4 + 3) * 132 + r_a] = va.w;
        xb[(kq * 4 + 0) * 132 + r_b] = vb.x;
        xb[(kq * 4 + 1) * 132 + r_b] = vb.y;
        xb[(kq * 4 + 2) * 132 + r_b] = vb.z;
        xb[(kq * 4 + 3) * 132 + r_b] = vb.w;
        __syncthreads();

        int kc1 = kc + 1;
        if (kc1 < nkc) {   // prefetch next chunk (overlaps with compute below)
            int seg = kc1 >> 2;          // 0: h, 1: agg1, 2: aggG (bus only)
            int kk  = (kc1 & 3) * 16 + kq * 4;
            const float* base = (seg == 0) ? hsrc : (seg == 1) ? agg1 : g_aggG;
            va = *(const float4*)(base + (size_t)grA * 64 + kk);
            vb = *(const float4*)(base + (size_t)grB * 64 + kk);
        }

        const float* wk = sW + kc * 1024 + tc * 4;   // 16 k-rows of 64 cols
        const float* xk = xb + tr * 8;
#pragma unroll
        for (int k = 0; k < 16; k++) {
            float4 w  = *(const float4*)(wk + k * 64);
            float4 x0 = *(const float4*)(xk + k * 132);
            float4 x1 = *(const float4*)(xk + k * 132 + 4);
            unsigned long long w01 = packf2b(w.x, w.y);
            unsigned long long w23 = packf2b(w.z, w.w);
            unsigned long long xx;
            xx = packf2(x0.x); fma2(acc[0],  xx, w01); fma2(acc[1],  xx, w23);
            xx = packf2(x0.y); fma2(acc[2],  xx, w01); fma2(acc[3],  xx, w23);
            xx = packf2(x0.z); fma2(acc[4],  xx, w01); fma2(acc[5],  xx, w23);
            xx = packf2(x0.w); fma2(acc[6],  xx, w01); fma2(acc[7],  xx, w23);
            xx = packf2(x1.x); fma2(acc[8],  xx, w01); fma2(acc[9],  xx, w23);
            xx = packf2(x1.y); fma2(acc[10], xx, w01); fma2(acc[11], xx, w23);
            xx = packf2(x1.z); fma2(acc[12], xx, w01); fma2(acc[13], xx, w23);
            xx = packf2(x1.w); fma2(acc[14], xx, w01); fma2(acc[15], xx, w23);
        }
        // single sync per iter is safe: next iter's STS targets the other buffer
    }

    // epilogue: relu + store 8x4 tile
    float* outp = bus ? g_hb : g_hg;
#pragma unroll
    for (int r = 0; r < 8; r++) {
        int rr = row0 + tr * 8 + r;
        if (rr < n) {
            float4 o;
            unpackf2(acc[2 * r],     o.x, o.y);
            unpackf2(acc[2 * r + 1], o.z, o.w);
            o.x = fmaxf(o.x, 0.f); o.y = fmaxf(o.y, 0.f);
            o.z = fmaxf(o.z, 0.f); o.w = fmaxf(o.w, 0.f);
            *(float4*)(outp + (size_t)rr * 64 + tc * 4) = o;
        }
    }
}

// ---------------- sum pooling (bus + gen) + cnt re-zero for next call ----------------
__global__ void k_pool_all() {
    // re-zero CSR counters (consumed this call; next call/replay needs zeros)
    for (int i = blockIdx.x * 256 + threadIdx.x; i < NBS; i += 300 * 256) {
        g_cntL[i] = 0; g_cntG[i] = 0;
        if (i < NGS) g_cntB[i] = 0;
    }

    bool bus = blockIdx.x < 240;
    const float* h = bus ? g_hb : g_hg;
    int n = bus ? NBS : NGS;
    int obase = bus ? 0 : 64;
    int bid = bus ? blockIdx.x : blockIdx.x - 240;
    int nb  = bus ? 240 : 60;

    int col = threadIdx.x & 63, grp = threadIdx.x >> 6;
    float s = 0.f;
    for (int r = bid * 4 + grp; r < n; r += nb * 4)
        s += h[(size_t)r * 64 + col];
    __shared__ float sh[256];
    sh[threadIdx.x] = s;
    __syncthreads();
    if (grp == 0)
        atomicAdd(&g_pool[obase + col],
                  sh[col] + sh[col + 64] + sh[col + 128] + sh[col + 192]);
}

// ---------------- MLP head (also re-zeroes g_pool for next call) ----------------
__global__ void k_head(const float* __restrict__ W_h, const float* __restrict__ b_h,
                       const float* __restrict__ W_o, const float* __restrict__ b_o,
                       float* __restrict__ out)
{
    __shared__ float sg[128], st[64];
    int t = threadIdx.x;   // 128 threads
    sg[t] = g_pool[t];
    __syncthreads();
    g_pool[t] = 0.f;       // consumed; restore zero-invariant for replay
    if (t < 64) {
        float a = b_h[t];
#pragma unroll
        for (int i = 0; i < 128; i++) a += sg[i] * W_h[i * 64 + t];
        st[t] = fmaxf(a, 0.f);
    }
    __syncthreads();
    if (t < 16) {
        float o = b_o[t];
#pragma unroll
        for (int j = 0; j < 64; j++) o += st[j] * W_o[j * 16 + t];
        out[t] = o;
    }
}

// ---------------- launch ----------------
extern "C" void kernel_launch(void* const* d_in, const int* in_sizes, int n_in,
                              void* d_out, int out_size)
{
    const float* x_bus   = (const float*)d_in[0];
    const float* x_gen   = (const float*)d_in[1];
    const int* line_src  = (const int*)d_in[2];
    const int* line_dst  = (const int*)d_in[3];
    const int* g2b_src   = (const int*)d_in[4];
    const int* g2b_dst   = (const int*)d_in[5];
    const int* b2g_src   = (const int*)d_in[6];
    const int* b2g_dst   = (const int*)d_in[7];
    const float* Wsb[2]  = { (const float*)d_in[8],  (const float*)d_in[15] };
    const float* Wsg[2]  = { (const float*)d_in[9],  (const float*)d_in[16] };
    const float* Wl[2]   = { (const float*)d_in[10], (const float*)d_in[17] };
    const float* Wg2b[2] = { (const float*)d_in[11], (const float*)d_in[18] };
    const float* Wb2g[2] = { (const float*)d_in[12], (const float*)d_in[19] };
    const float* bsb[2]  = { (const float*)d_in[13], (const float*)d_in[20] };
    const float* bsg[2]  = { (const float*)d_in[14], (const float*)d_in[21] };
    const float* W_h = (const float*)d_in[22];
    const float* b_h = (const float*)d_in[23];
    const float* W_o = (const float*)d_in[24];
    const float* b_o = (const float*)d_in[25];

    const int SMEM_FUSED = (12288 + 64 + 2 * 16 * 132) * 4;   // 66304 B
    cudaFuncSetAttribute(k_fused, cudaFuncAttributeMaxDynamicSharedMemorySize,
                         SMEM_FUSED);

    const int GATH_BLOCKS = ((2 * NBS + NGS) * 8 + 255) / 256;  // 6875

    // launch order chosen so launch #4 (= the ncu capture slot) is the
    // layer-2 k_gather (verifies the MLP improvement)
    k_fill<<<(EL + 255) / 256, 256>>>(line_src, line_dst,                 // 1
                                      g2b_src, g2b_dst, b2g_src, b2g_dst);
    k_gather<<<GATH_BLOCKS, 256>>>(x_bus, x_gen);                         // 2
    k_fused<<<BUSB + GENB, 256, SMEM_FUSED>>>(x_bus, x_gen,               // 3
                                  Wsb[0], Wl[0], Wg2b[0], bsb[0],
                                  Wsg[0], Wb2g[0], bsg[0]);
    k_gather<<<GATH_BLOCKS, 256>>>(nullptr, nullptr);                     // 4 (ncu)
    k_fused<<<BUSB + GENB, 256, SMEM_FUSED>>>(nullptr, nullptr,           // 5
                                  Wsb[1], Wl[1], Wg2b[1], bsb[1],
                                  Wsg[1], Wb2g[1], bsg[1]);
    k_pool_all<<<300, 256>>>();                                           // 6
    k_head<<<1, 128>>>(W_h, b_h, W_o, b_o, (float*)d_out);                // 7
}